// round 11
// baseline (speedup 1.0000x reference)
#include <cuda_runtime.h>
#include <math.h>

#define MM      128
#define MP1     129
#define DD      24
#define NN      512
#define LL      256
#define MSTRIDE 132

#define EMINE   (-(1 << 27))
#define LOG2E   1.4426950408889634f
#define LN2     0.6931471805599453f

// ---------------- device-global scratch (probability domain) ----------------
__device__ __align__(16) float g_cb0[MSTRIDE];
__device__ __align__(16) float g_cb1[MSTRIDE];
__device__ __align__(16) float g_w  [MSTRIDE];
__device__ __align__(16) float g_q00[MSTRIDE];
__device__ __align__(16) float g_q10[MSTRIDE];
__device__ __align__(16) float g_q01[MSTRIDE];
__device__ __align__(16) float g_q11[MSTRIDE];
__device__ __align__(16) float g_c0 [MSTRIDE];
__device__ __align__(16) float g_c1 [MSTRIDE];
__device__ __align__(16) float g_Ea [(DD + 1) * MSTRIDE];  // emission probs; row DD = 1.0 (padding)
__device__ __align__(16) float g_Ei [(DD + 1) * MSTRIDE];
__device__ __align__(16) int   g_tok[NN * LL];

struct FalseT { static constexpr bool value = false; };
struct TrueT  { static constexpr bool value = true;  };

// ---- extended float primitives: value = m * 2^e ----
__device__ __forceinline__ float escf(float x, int k) {
    k = max(k, -140);
    int b = __float_as_int(x) + (k << 23);
    return __int_as_float(max(b, 0x00800000));
}
__device__ __forceinline__ void enorm2(float& m0, float& m1, int& e) {
    float mx = fmaxf(m0, m1);
    int k = (__float_as_int(mx) >> 23) - 127;
    int s = k << 23;
    m0 = __int_as_float(max(__float_as_int(m0) - s, 0));
    m1 = __int_as_float(max(__float_as_int(m1) - s, 0));
    e += k;
}
__device__ __forceinline__ void enorm1(float& m, int& e) {
    int b = __float_as_int(m);
    int k = (b >> 23) - 127;
    e += k;
    m = __int_as_float(b - (k << 23));
}

__device__ __forceinline__ float lse2_acc(float a, float b) {  // prep only
    float mx = fmaxf(a, b);
    float mn = fminf(a, b);
    return mx + log1pf(expf(mn - mx));
}

// ---------------- fused prep ----------------
__global__ void prep(const float* __restrict__ anc,
                     const float* __restrict__ ins,
                     const float* __restrict__ rr,
                     const float* __restrict__ uu,
                     const float* __restrict__ data) {
    int b = blockIdx.x;
    if (b < NN) {
        int t = threadIdx.x;
        const float* row = data + ((size_t)(b * LL + t)) * DD;
        int tk = DD;
        for (int d = 0; d < DD; d++)
            if (row[d] > 0.5f) tk = d;
        g_tok[b * LL + t] = tk;
        return;
    }

    int m = threadIdx.x;
    if (m < MSTRIDE) {
        g_Ea[DD * MSTRIDE + m] = 1.0f;
        g_Ei[DD * MSTRIDE + m] = 1.0f;
    }
    if (m >= MP1) return;

    {
        const float* ar = anc + m * DD;
        float mx = -1e30f;
        for (int d = 0; d < DD; d++) mx = fmaxf(mx, ar[d]);
        float s = 0.f;
        for (int d = 0; d < DD; d++) s += expf(ar[d] - mx);
        float lse = mx + logf(s);
        for (int d = 0; d < DD; d++) g_Ea[d * MSTRIDE + m] = expf(ar[d] - lse);
    }
    {
        const float* ir = ins + m * DD;
        float mx = -1e30f;
        for (int d = 0; d < DD; d++) mx = fmaxf(mx, ir[d]);
        float s = 0.f;
        for (int d = 0; d < DD; d++) s += expf(ir[d] - mx);
        float lse = mx + logf(s);
        for (int d = 0; d < DD; d++) g_Ei[d * MSTRIDE + m] = expf(ir[d] - lse);
    }

    float r[3][2], u[3][2];
    for (int c = 0; c < 3; c++) {
        float x0 = rr[(m * 3 + c) * 2 + 0];
        float x1 = rr[(m * 3 + c) * 2 + 1];
        float l2 = lse2_acc(x0, x1);
        r[c][0] = x0 - l2; r[c][1] = x1 - l2;
        x0 = uu[(m * 3 + c) * 2 + 0];
        x1 = uu[(m * 3 + c) * 2 + 1];
        l2 = lse2_acc(x0, x1);
        u[c][0] = x0 - l2; u[c][1] = x1 - l2;
    }
    g_w  [m] = expf(r[2][0] + u[2][1]);
    g_cb0[m] = expf(r[0][0] + u[0][1]);
    g_cb1[m] = expf(r[1][0] + u[1][1]);
    g_q00[m] = expf(r[0][0] + u[0][0]);
    g_q10[m] = expf(r[1][0] + u[1][0]);
    g_q01[m] = expf(r[0][1]);
    g_q11[m] = expf(r[1][1]);
    g_c0 [m] = expf(r[2][0] + u[2][0]);
    g_c1 [m] = expf(r[2][1]);
}

// per-sequence recurrent state
struct SeqState {
    float a0m[4], a1m[4];
    int   ae[4];
    float axm1; int axe;       // insert state m=128
    float axm0; int axe0;      // match state m=128 (last step only)
    float srcm; int srce;      // virtual source
};

// ---------------- main: 4 warps/block, TWO sequences per warp ----------------
__global__ void __launch_bounds__(128) hmm_fwd(float* __restrict__ out) {
    const unsigned FULL = 0xffffffffu;
    const int wid = threadIdx.x >> 5;
    const int nA = (blockIdx.x * 4 + wid) * 2;
    const int nB = nA + 1;
    const int l = threadIdx.x & 31;
    const int m0 = l * 4;
    const bool lastlane = (l == 31);

    float cb0[4], cb1[4], wv[4], q00[4], q10[4], q01[4], q11[4], c0[4], c1[4];
#pragma unroll
    for (int q = 0; q < 4; q++) {
        int m = m0 + q;
        cb0[q] = g_cb0[m]; cb1[q] = g_cb1[m]; wv[q] = g_w[m];
        q00[q] = g_q00[m]; q10[q] = g_q10[m];
        q01[q] = g_q01[m]; q11[q] = g_q11[m];
        c0[q]  = g_c0[m];  c1[q]  = g_c1[m];
    }
    const float q00x = lastlane ? g_q00[MM] : 0.f;
    const float q10x = lastlane ? g_q10[MM] : 0.f;
    const float q01x = lastlane ? g_q01[MM] : 0.f;
    const float q11x = lastlane ? g_q11[MM] : 0.f;
    const float c0x  = lastlane ? g_c0 [MM] : 0.f;
    const float c1x  = lastlane ? g_c1 [MM] : 0.f;

    const float wv0 = wv[0], wv1 = wv[1], wv2 = wv[2], wv3 = wv[3];
    const float W23  = wv2 * wv3;
    const float W123 = wv1 * W23;
    const float cbW0 = cb0[0] * W123;
    const float cbW1 = cb1[0] * W123;

    // lane-aggregate multiplier prefix; scan K constants as (m, e)
    float Lwl = log2f(wv0 * W123);
    float P = Lwl;
#pragma unroll
    for (int d = 1; d < 32; d <<= 1) {
        float o = __shfl_up_sync(FULL, P, d);
        if (l >= d) P += o;
    }
    float Km[10]; int Ke[10];
    {
        const int offs[10] = {1, 2, 3, 4, 5, 6, 7, 8, 16, 24};
#pragma unroll
        for (int j = 0; j < 10; j++) {
            float Po = __shfl_up_sync(FULL, P, offs[j]);
            if (l >= offs[j]) {
                float Kl = P - Po;
                float fe = floorf(Kl);
                Ke[j] = (int)fe;
                Km[j] = exp2f(Kl - fe);
            } else { Km[j] = 0.f; Ke[j] = EMINE; }
        }
    }

    SeqState A, B;
#pragma unroll
    for (int i = 0; i < 4; i++) {
        A.a0m[i] = A.a1m[i] = 0.f; A.ae[i] = EMINE;
        B.a0m[i] = B.a1m[i] = 0.f; B.ae[i] = EMINE;
    }
    A.axm1 = 0.f; A.axe = EMINE; A.axm0 = 0.f; A.axe0 = EMINE; A.srcm = 1.0f; A.srce = 0;
    B.axm1 = 0.f; B.axe = EMINE; B.axm0 = 0.f; B.axe0 = EMINE; B.srcm = 1.0f; B.srce = 0;

    const int* tnA = g_tok + nA * LL;
    const int* tnB = g_tok + nB * LL;

    // one HMM step for one sequence
    auto step = [&](SeqState& st, float4 eaC, float4 eiC, float eixC, int tkoC, auto LASTC) {
        constexpr bool LAST = decltype(LASTC)::value;

        float atopm = __shfl_up_sync(FULL, st.a0m[3], 1);
        int   atope = __shfl_up_sync(FULL, st.ae[3], 1);
        if (l == 0) { atopm = st.srcm; atope = st.srce; }

        float bm[4], t0[4], t1[4], u0;
        int e2[4];
#pragma unroll
        for (int i = 0; i < 4; i++) {
            float Pm = (i == 0) ? atopm : st.a0m[i - 1];
            int   Pe = (i == 0) ? atope : st.ae[i - 1];
            int e = max(Pe, st.ae[i]);
            float ps = escf(Pm, Pe - e);
            float is = escf(st.a1m[i], st.ae[i] - e);
            e2[i] = e;
            bm[i] = ps * cb0[i] + is * cb1[i];
            t0[i] = ps * q00[i] + is * q10[i];
            t1[i] = ps * q01[i] + is * q11[i];
            if (i == 0) u0 = ps * cbW0 + is * cbW1;
        }
        // m=128 element (insert only during mainloop)
        int e2x = max(st.ae[3], st.axe);
        float psx = escf(st.a0m[3], st.ae[3] - e2x);
        float isx = escf(st.axm1, st.axe - e2x);
        float t1x = psx * q01x + isx * q11x;
        float t0x = 0.f;
        if (LAST) t0x = psx * q00x + isx * q10x;

        // lane aggregate injection
        int Bse = max(max(e2[0], e2[1]), max(e2[2], e2[3]));
        float Bsm = escf(u0, e2[0] - Bse) + escf(bm[1] * W23, e2[1] - Bse)
                  + escf(bm[2] * wv3, e2[2] - Bse) + escf(bm[3], e2[3] - Bse);

        // warp scan: radix-8 round (offsets 1..7), then radix-4 round (8,16,24)
        {
            float om[7]; int oe[7];
#pragma unroll
            for (int j = 0; j < 7; j++) {
                om[j] = __shfl_up_sync(FULL, Bsm, j + 1) * Km[j];
                oe[j] = __shfl_up_sync(FULL, Bse, j + 1) + Ke[j];
            }
            int E = Bse;
#pragma unroll
            for (int j = 0; j < 7; j++) E = max(E, oe[j]);
            float s = escf(Bsm, Bse - E);
#pragma unroll
            for (int j = 0; j < 7; j++) s += escf(om[j], oe[j] - E);
            Bsm = s; Bse = E;

            float p1m = __shfl_up_sync(FULL, Bsm, 8)  * Km[7];
            int   p1e = __shfl_up_sync(FULL, Bse, 8)  + Ke[7];
            float p2m = __shfl_up_sync(FULL, Bsm, 16) * Km[8];
            int   p2e = __shfl_up_sync(FULL, Bse, 16) + Ke[8];
            float p3m = __shfl_up_sync(FULL, Bsm, 24) * Km[9];
            int   p3e = __shfl_up_sync(FULL, Bse, 24) + Ke[9];
            E = max(max(Bse, p1e), max(p2e, p3e));
            Bsm = escf(Bsm, Bse - E) + escf(p1m, p1e - E)
                + escf(p2m, p2e - E) + escf(p3m, p3e - E);
            Bse = E;
        }
        float Bexm = __shfl_up_sync(FULL, Bsm, 1);
        int   Bexe = __shfl_up_sync(FULL, Bse, 1);
        if (l == 0) { Bexm = 0.f; Bexe = EMINE; }

        const float eav[4] = {eaC.x, eaC.y, eaC.z, eaC.w};
        const float eiv[4] = {eiC.x, eiC.y, eiC.z, eiC.w};

        // fused B-chain + na-phase: E_i = Be_{i+1}, zs shared
        float Bm = Bexm; int Be = Bexe;
#pragma unroll
        for (int i = 0; i < 4; i++) {
            int En = max(Be, e2[i]);
            float zs = escf(Bm, Be - En);
            int kk = e2[i] - En;
            float s0 = escf(t0[i], kk) + zs * c0[i];
            float s1 = escf(t1[i], kk) + zs * c1[i];
            st.a0m[i] = s0 * eav[i];
            st.a1m[i] = s1 * eiv[i];
            st.ae[i] = En;
            if (i < 3) { Bm = zs * wv[i] + escf(bm[i], kk); Be = En; }
        }
        {
            int E = max(e2x, Bse);
            float zs = escf(Bsm, Bse - E);
            int kk = e2x - E;
            st.axm1 = (escf(t1x, kk) + zs * c1x) * eixC;
            if (LAST) {
                float eax = g_Ea[tkoC + MM];
                st.axm0 = (escf(t0x, kk) + zs * c0x) * eax;
                st.axe0 = E;
            }
            st.axe = E;
        }
        st.srcm = 0.f; st.srce = EMINE;
    };

    auto renorm = [&](SeqState& st) {
#pragma unroll
        for (int i = 0; i < 4; i++) enorm2(st.a0m[i], st.a1m[i], st.ae[i]);
        enorm1(st.axm1, st.axe);
    };

    // ---------------- pipelined mainloop (group of 2 steps) ----------------
    int2 tkcA = *(const int2*)(tnA);
    int2 tkcB = *(const int2*)(tnB);
    int tkoA = tkcA.x * MSTRIDE, tkoB = tkcB.x * MSTRIDE;
    float4 eaA = *(const float4*)(g_Ea + tkoA + m0);
    float4 eiA = *(const float4*)(g_Ei + tkoA + m0);
    float eixA = g_Ei[tkoA + MM];
    float4 eaB = *(const float4*)(g_Ea + tkoB + m0);
    float4 eiB = *(const float4*)(g_Ei + tkoB + m0);
    float eixB = g_Ei[tkoB + MM];

    for (int tt = 0; tt < LL - 2; tt += 2) {
        const int2 tknA = *(const int2*)(tnA + tt + 2);
        const int2 tknB = *(const int2*)(tnB + tt + 2);
        const int ntA[2] = {tkcA.y, tknA.x};
        const int ntB[2] = {tkcB.y, tknB.x};
#pragma unroll
        for (int k = 0; k < 2; k++) {
            const int tko2A = ntA[k] * MSTRIDE;
            const float4 eaA2 = *(const float4*)(g_Ea + tko2A + m0);
            const float4 eiA2 = *(const float4*)(g_Ei + tko2A + m0);
            const float eixA2 = g_Ei[tko2A + MM];
            const int tko2B = ntB[k] * MSTRIDE;
            const float4 eaB2 = *(const float4*)(g_Ea + tko2B + m0);
            const float4 eiB2 = *(const float4*)(g_Ei + tko2B + m0);
            const float eixB2 = g_Ei[tko2B + MM];

            step(A, eaA, eiA, eixA, 0, FalseT{});
            step(B, eaB, eiB, eixB, 0, FalseT{});
            eaA = eaA2; eiA = eiA2; eixA = eixA2;
            eaB = eaB2; eiB = eiB2; eixB = eixB2;
        }
        renorm(A); renorm(B);
        tkcA = tknA; tkcB = tknB;
    }
    // final group: steps 254, 255 (255 computes m=128 match state)
    {
        const int tko2A = tkcA.y * MSTRIDE;
        const float4 eaA2 = *(const float4*)(g_Ea + tko2A + m0);
        const float4 eiA2 = *(const float4*)(g_Ei + tko2A + m0);
        const float eixA2 = g_Ei[tko2A + MM];
        const int tko2B = tkcB.y * MSTRIDE;
        const float4 eaB2 = *(const float4*)(g_Ea + tko2B + m0);
        const float4 eiB2 = *(const float4*)(g_Ei + tko2B + m0);
        const float eixB2 = g_Ei[tko2B + MM];

        step(A, eaA, eiA, eixA, 0, FalseT{});
        step(B, eaB, eiB, eixB, 0, FalseT{});
        step(A, eaA2, eiA2, eixA2, tko2A, TrueT{});
        step(B, eaB2, eiB2, eixB2, tko2B, TrueT{});
    }

    // final logsumexp for both sequences
    auto finish = [&](SeqState& st) -> float {
        int emax = max(st.axe, st.axe0);
#pragma unroll
        for (int q = 0; q < 4; q++) emax = max(emax, st.ae[q]);
#pragma unroll
        for (int d = 16; d; d >>= 1) emax = max(emax, __shfl_xor_sync(FULL, emax, d));
        float s = escf(st.axm0, st.axe0 - emax) + escf(st.axm1, st.axe - emax);
#pragma unroll
        for (int q = 0; q < 4; q++)
            s += escf(st.a0m[q], st.ae[q] - emax) + escf(st.a1m[q], st.ae[q] - emax);
#pragma unroll
        for (int d = 16; d; d >>= 1) s += __shfl_xor_sync(FULL, s, d);
        return ((float)emax + log2f(s)) * LN2;
    };

    float rA = finish(A);
    float rB = finish(B);
    if (l == 0) {
        out[nA] = rA;
        out[nB] = rB;
    }
}

// ---------------- entry point ----------------
extern "C" void kernel_launch(void* const* d_in, const int* in_sizes, int n_in,
                              void* d_out, int out_size) {
    const float* anc  = (const float*)d_in[0];  // (129, 24)
    const float* ins  = (const float*)d_in[1];  // (129, 24)
    const float* rr   = (const float*)d_in[2];  // (129, 3, 2)
    const float* uu   = (const float*)d_in[3];  // (129, 3, 2)
    const float* data = (const float*)d_in[4];  // (512, 256, 24)
    (void)in_sizes; (void)n_in; (void)out_size;

    prep<<<NN + 1, LL>>>(anc, ins, rr, uu, data);
    hmm_fwd<<<NN / 8, 128>>>((float*)d_out);   // 64 blocks x 4 warps x 2 seqs
}

// round 12
// speedup vs baseline: 1.6534x; 1.6534x over previous
#include <cuda_runtime.h>
#include <math.h>

#define MM      128
#define MP1     129
#define DD      24
#define NN      512
#define LL      256
#define MSTRIDE 132

#define EMINE   (-(1 << 27))
#define LOG2E   1.4426950408889634f
#define LN2     0.6931471805599453f

// ---------------- device-global scratch (probability domain) ----------------
__device__ __align__(16) float g_cb0[MSTRIDE];
__device__ __align__(16) float g_cb1[MSTRIDE];
__device__ __align__(16) float g_w  [MSTRIDE];
__device__ __align__(16) float g_q00[MSTRIDE];
__device__ __align__(16) float g_q10[MSTRIDE];
__device__ __align__(16) float g_q01[MSTRIDE];
__device__ __align__(16) float g_q11[MSTRIDE];
__device__ __align__(16) float g_c0 [MSTRIDE];
__device__ __align__(16) float g_c1 [MSTRIDE];
__device__ __align__(16) float g_Ea [(DD + 1) * MSTRIDE];  // emission probs; row DD = 1.0 (padding)
__device__ __align__(16) float g_Ei [(DD + 1) * MSTRIDE];
__device__ __align__(16) int   g_tok[NN * LL];

struct FalseT { static constexpr bool value = false; };
struct TrueT  { static constexpr bool value = true;  };

// ---- extended float primitives: value = m * 2^e ----
__device__ __forceinline__ float escf(float x, int k) {
    k = max(k, -140);
    int b = __float_as_int(x) + (k << 23);
    return __int_as_float(max(b, 0x00800000));
}
__device__ __forceinline__ void enorm2(float& m0, float& m1, int& e) {
    float mx = fmaxf(m0, m1);
    int k = (__float_as_int(mx) >> 23) - 127;
    int s = k << 23;
    m0 = __int_as_float(max(__float_as_int(m0) - s, 0));
    m1 = __int_as_float(max(__float_as_int(m1) - s, 0));
    e += k;
}
__device__ __forceinline__ void enorm1(float& m, int& e) {
    int b = __float_as_int(m);
    int k = (b >> 23) - 127;
    e += k;
    m = __int_as_float(b - (k << 23));
}

__device__ __forceinline__ float lse2_acc(float a, float b) {  // prep only
    float mx = fmaxf(a, b);
    float mn = fminf(a, b);
    return mx + log1pf(expf(mn - mx));
}

// ---------------- fused prep ----------------
__global__ void prep(const float* __restrict__ anc,
                     const float* __restrict__ ins,
                     const float* __restrict__ rr,
                     const float* __restrict__ uu,
                     const float* __restrict__ data) {
    int b = blockIdx.x;
    if (b < NN) {
        int t = threadIdx.x;
        const float* row = data + ((size_t)(b * LL + t)) * DD;
        int tk = DD;
        for (int d = 0; d < DD; d++)
            if (row[d] > 0.5f) tk = d;
        g_tok[b * LL + t] = tk;
        return;
    }

    int m = threadIdx.x;
    if (m < MSTRIDE) {
        g_Ea[DD * MSTRIDE + m] = 1.0f;
        g_Ei[DD * MSTRIDE + m] = 1.0f;
    }
    if (m >= MP1) return;

    {
        const float* ar = anc + m * DD;
        float mx = -1e30f;
        for (int d = 0; d < DD; d++) mx = fmaxf(mx, ar[d]);
        float s = 0.f;
        for (int d = 0; d < DD; d++) s += expf(ar[d] - mx);
        float lse = mx + logf(s);
        for (int d = 0; d < DD; d++) g_Ea[d * MSTRIDE + m] = expf(ar[d] - lse);
    }
    {
        const float* ir = ins + m * DD;
        float mx = -1e30f;
        for (int d = 0; d < DD; d++) mx = fmaxf(mx, ir[d]);
        float s = 0.f;
        for (int d = 0; d < DD; d++) s += expf(ir[d] - mx);
        float lse = mx + logf(s);
        for (int d = 0; d < DD; d++) g_Ei[d * MSTRIDE + m] = expf(ir[d] - lse);
    }

    float r[3][2], u[3][2];
    for (int c = 0; c < 3; c++) {
        float x0 = rr[(m * 3 + c) * 2 + 0];
        float x1 = rr[(m * 3 + c) * 2 + 1];
        float l2 = lse2_acc(x0, x1);
        r[c][0] = x0 - l2; r[c][1] = x1 - l2;
        x0 = uu[(m * 3 + c) * 2 + 0];
        x1 = uu[(m * 3 + c) * 2 + 1];
        l2 = lse2_acc(x0, x1);
        u[c][0] = x0 - l2; u[c][1] = x1 - l2;
    }
    g_w  [m] = expf(r[2][0] + u[2][1]);
    g_cb0[m] = expf(r[0][0] + u[0][1]);
    g_cb1[m] = expf(r[1][0] + u[1][1]);
    g_q00[m] = expf(r[0][0] + u[0][0]);
    g_q10[m] = expf(r[1][0] + u[1][0]);
    g_q01[m] = expf(r[0][1]);
    g_q11[m] = expf(r[1][1]);
    g_c0 [m] = expf(r[2][0] + u[2][0]);
    g_c1 [m] = expf(r[2][1]);
}

// ---------------- main: 4 warps/block (one per SMSP), one sequence per warp ----------------
__global__ void __launch_bounds__(128) hmm_fwd(float* __restrict__ out) {
    const unsigned FULL = 0xffffffffu;
    const int wid = threadIdx.x >> 5;
    const int n = blockIdx.x * 4 + wid;
    const int l = threadIdx.x & 31;
    const int m0 = l * 4;
    const bool lastlane = (l == 31);

    float cb0[4], cb1[4], wv[4], q00[4], q10[4], q01[4], q11[4], c0[4], c1[4];
#pragma unroll
    for (int q = 0; q < 4; q++) {
        int m = m0 + q;
        cb0[q] = g_cb0[m]; cb1[q] = g_cb1[m]; wv[q] = g_w[m];
        q00[q] = g_q00[m]; q10[q] = g_q10[m];
        q01[q] = g_q01[m]; q11[q] = g_q11[m];
        c0[q]  = g_c0[m];  c1[q]  = g_c1[m];
    }
    const float q00x = lastlane ? g_q00[MM] : 0.f;
    const float q10x = lastlane ? g_q10[MM] : 0.f;
    const float q01x = lastlane ? g_q01[MM] : 0.f;
    const float q11x = lastlane ? g_q11[MM] : 0.f;
    const float c0x  = lastlane ? g_c0 [MM] : 0.f;
    const float c1x  = lastlane ? g_c1 [MM] : 0.f;

    const float wv0 = wv[0], wv1 = wv[1], wv2 = wv[2], wv3 = wv[3];
    const float W23  = wv2 * wv3;
    const float W12  = wv1 * wv2;
    const float Wp2  = wv0 * wv1 * wv2;
    const float W123 = wv1 * W23;
    const float cbW0 = cb0[0] * W123;
    const float cbW1 = cb1[0] * W123;

    // lane-aggregate multiplier prefix; scan K constants as (m, e)
    float Lwl = log2f(wv0 * W123);
    float P = Lwl;
#pragma unroll
    for (int d = 1; d < 32; d <<= 1) {
        float o = __shfl_up_sync(FULL, P, d);
        if (l >= d) P += o;
    }
    float Km[10]; int Ke[10];
    {
        const int offs[10] = {1, 2, 3, 4, 5, 6, 7, 8, 16, 24};
#pragma unroll
        for (int j = 0; j < 10; j++) {
            float Po = __shfl_up_sync(FULL, P, offs[j]);
            if (l >= offs[j]) {
                float Kl = P - Po;
                float fe = floorf(Kl);
                Ke[j] = (int)fe;
                Km[j] = exp2f(Kl - fe);
            } else { Km[j] = 0.f; Ke[j] = EMINE; }
        }
    }

    // state
    float a0m[4] = {0.f, 0.f, 0.f, 0.f}, a1m[4] = {0.f, 0.f, 0.f, 0.f};
    int   ae[4]  = {EMINE, EMINE, EMINE, EMINE};
    float axm1 = 0.f; int axe = EMINE;      // insert state m=128
    float axm0 = 0.f; int axe0 = EMINE;     // match state m=128 (final step only)
    float srcm = 1.0f; int srce = 0;

    const int* tn = g_tok + n * LL;

    // one HMM step; LAST variant additionally computes the m=128 match state
    auto step = [&](int tkoC, float4 eaC, float4 eiC, float eixC, auto LASTC) {
        constexpr bool LAST = decltype(LASTC)::value;

        float atopm = __shfl_up_sync(FULL, a0m[3], 1);
        int   atope = __shfl_up_sync(FULL, ae[3], 1);
        if (l == 0) { atopm = srcm; atope = srce; }

        float bm[4], t0[4], t1[4], u0;
        int e2[4];
#pragma unroll
        for (int i = 0; i < 4; i++) {
            float Pm = (i == 0) ? atopm : a0m[i - 1];
            int   Pe = (i == 0) ? atope : ae[i - 1];
            int e = max(Pe, ae[i]);
            float ps = escf(Pm, Pe - e);
            float is = escf(a1m[i], ae[i] - e);
            e2[i] = e;
            bm[i] = ps * cb0[i] + is * cb1[i];
            t0[i] = ps * q00[i] + is * q10[i];
            t1[i] = ps * q01[i] + is * q11[i];
            if (i == 0) u0 = ps * cbW0 + is * cbW1;
        }
        // m=128 element (insert only during mainloop)
        int e2x = max(ae[3], axe);
        float psx = escf(a0m[3], ae[3] - e2x);
        float isx = escf(axm1, axe - e2x);
        float t1x = psx * q01x + isx * q11x;
        float t0x = 0.f;
        if (LAST) t0x = psx * q00x + isx * q10x;

        // lane aggregate injection (tree sum)
        int e01 = max(e2[0], e2[1]), e23 = max(e2[2], e2[3]);
        int Bse = max(e01, e23);
        float Bsm = (escf(u0, e2[0] - Bse) + escf(bm[1] * W23, e2[1] - Bse))
                  + (escf(bm[2] * wv3, e2[2] - Bse) + escf(bm[3], e2[3] - Bse));

        // warp scan: radix-8 round (offsets 1..7), then radix-4 round (8,16,24)
        {
            float om[7]; int oe[7];
#pragma unroll
            for (int j = 0; j < 7; j++) {
                om[j] = __shfl_up_sync(FULL, Bsm, j + 1) * Km[j];
                oe[j] = __shfl_up_sync(FULL, Bse, j + 1) + Ke[j];
            }
            // max tree
            int Ea = max(Bse, oe[0]), Eb = max(oe[1], oe[2]);
            int Ec = max(oe[3], oe[4]), Ed = max(oe[5], oe[6]);
            int E = max(max(Ea, Eb), max(Ec, Ed));
            // sum tree
            float sa = escf(Bsm, Bse - E) + escf(om[0], oe[0] - E);
            float sb = escf(om[1], oe[1] - E) + escf(om[2], oe[2] - E);
            float sc = escf(om[3], oe[3] - E) + escf(om[4], oe[4] - E);
            float sd = escf(om[5], oe[5] - E) + escf(om[6], oe[6] - E);
            Bsm = (sa + sb) + (sc + sd);
            Bse = E;

            float p1m = __shfl_up_sync(FULL, Bsm, 8)  * Km[7];
            int   p1e = __shfl_up_sync(FULL, Bse, 8)  + Ke[7];
            float p2m = __shfl_up_sync(FULL, Bsm, 16) * Km[8];
            int   p2e = __shfl_up_sync(FULL, Bse, 16) + Ke[8];
            float p3m = __shfl_up_sync(FULL, Bsm, 24) * Km[9];
            int   p3e = __shfl_up_sync(FULL, Bse, 24) + Ke[9];
            E = max(max(Bse, p1e), max(p2e, p3e));
            Bsm = (escf(Bsm, Bse - E) + escf(p1m, p1e - E))
                + (escf(p2m, p2e - E) + escf(p3m, p3e - E));
            Bse = E;
        }
        float Bexm = __shfl_up_sync(FULL, Bsm, 1);
        int   Bexe = __shfl_up_sync(FULL, Bse, 1);
        if (l == 0) { Bexm = 0.f; Bexe = EMINE; }

        const float eav[4] = {eaC.x, eaC.y, eaC.z, eaC.w};
        const float eiv[4] = {eiC.x, eiC.y, eiC.z, eiC.w};

        // ---- element 3 FIRST via flattened B3 (releases a0m[3]/ae[3] early
        //      for the next step's critical shfl) ----
        {
            // Be3 = max(Bexe, e2[0..2]); En3 = max(Be3, e2[3])
            int Eb3 = max(max(Bexe, e2[0]), max(e2[1], e2[2]));
            int En3 = max(Eb3, e2[3]);
            float zs3 = (escf(Bexm, Bexe - En3) * Wp2
                       + escf(bm[0], e2[0] - En3) * W12)
                      + (escf(bm[1], e2[1] - En3) * wv2
                       + escf(bm[2], e2[2] - En3));
            int kk = e2[3] - En3;
            float s0 = escf(t0[3], kk) + zs3 * c0[3];
            float s1 = escf(t1[3], kk) + zs3 * c1[3];
            a0m[3] = s0 * eav[3];
            a1m[3] = s1 * eiv[3];
            ae[3] = En3;
        }
        // ---- elements 0..2 via recurrent chain (off critical path) ----
        {
            float Bm = Bexm; int Be = Bexe;
#pragma unroll
            for (int i = 0; i < 3; i++) {
                int En = max(Be, e2[i]);
                float zs = escf(Bm, Be - En);
                int kk = e2[i] - En;
                float s0 = escf(t0[i], kk) + zs * c0[i];
                float s1 = escf(t1[i], kk) + zs * c1[i];
                a0m[i] = s0 * eav[i];
                a1m[i] = s1 * eiv[i];
                ae[i] = En;
                if (i < 2) { Bm = zs * wv[i] + escf(bm[i], kk); Be = En; }
            }
        }
        // ---- m = 128 ----
        {
            int E = max(e2x, Bse);
            float zs = escf(Bsm, Bse - E);
            int kk = e2x - E;
            axm1 = (escf(t1x, kk) + zs * c1x) * eixC;
            if (LAST) {
                float eax = g_Ea[tkoC + MM];
                axm0 = (escf(t0x, kk) + zs * c0x) * eax;
                axe0 = E;
            }
            axe = E;
        }
        srcm = 0.f; srce = EMINE;
    };

    // ---------------- pipelined mainloop ----------------
    int4 tkc = *(const int4*)(tn);
    int tko = tkc.x * MSTRIDE;
    float4 ea = *(const float4*)(g_Ea + tko + m0);
    float4 ei = *(const float4*)(g_Ei + tko + m0);
    float eix = g_Ei[tko + MM];

    for (int tt = 0; tt < LL - 4; tt += 4) {
        const int4 tkn = *(const int4*)(tn + tt + 4);
        const int ct[4] = {tkc.x, tkc.y, tkc.z, tkc.w};
        const int nt[4] = {tkc.y, tkc.z, tkc.w, tkn.x};
#pragma unroll
        for (int k = 0; k < 4; k++) {
            const int tko2 = nt[k] * MSTRIDE;
            const float4 ea2 = *(const float4*)(g_Ea + tko2 + m0);
            const float4 ei2 = *(const float4*)(g_Ei + tko2 + m0);
            const float eix2 = g_Ei[tko2 + MM];

            step(ct[k] * MSTRIDE, ea, ei, eix, FalseT{});
            ea = ea2; ei = ei2; eix = eix2;

            if (k & 1) {
#pragma unroll
                for (int i = 0; i < 4; i++) enorm2(a0m[i], a1m[i], ae[i]);
                enorm1(axm1, axe);
            }
        }
        tkc = tkn;
    }
    // final group (tt = LL-4): steps 252..255; 255 also computes a0x
    {
        const int ct[4] = {tkc.x, tkc.y, tkc.z, tkc.w};
#pragma unroll
        for (int k = 0; k < 3; k++) {
            const int tko2 = ct[k + 1] * MSTRIDE;
            const float4 ea2 = *(const float4*)(g_Ea + tko2 + m0);
            const float4 ei2 = *(const float4*)(g_Ei + tko2 + m0);
            const float eix2 = g_Ei[tko2 + MM];
            step(ct[k] * MSTRIDE, ea, ei, eix, FalseT{});
            ea = ea2; ei = ei2; eix = eix2;
            if (k & 1) {
#pragma unroll
                for (int i = 0; i < 4; i++) enorm2(a0m[i], a1m[i], ae[i]);
                enorm1(axm1, axe);
            }
        }
        step(ct[3] * MSTRIDE, ea, ei, eix, TrueT{});
    }

    // final logsumexp over all states
    int emax = max(axe, axe0);
#pragma unroll
    for (int q = 0; q < 4; q++) emax = max(emax, ae[q]);
#pragma unroll
    for (int d = 16; d; d >>= 1) emax = max(emax, __shfl_xor_sync(FULL, emax, d));

    float s = escf(axm0, axe0 - emax) + escf(axm1, axe - emax);
#pragma unroll
    for (int q = 0; q < 4; q++)
        s += escf(a0m[q], ae[q] - emax) + escf(a1m[q], ae[q] - emax);
#pragma unroll
    for (int d = 16; d; d >>= 1) s += __shfl_xor_sync(FULL, s, d);

    if (l == 0) out[n] = ((float)emax + log2f(s)) * LN2;
}

// ---------------- entry point ----------------
extern "C" void kernel_launch(void* const* d_in, const int* in_sizes, int n_in,
                              void* d_out, int out_size) {
    const float* anc  = (const float*)d_in[0];  // (129, 24)
    const float* ins  = (const float*)d_in[1];  // (129, 24)
    const float* rr   = (const float*)d_in[2];  // (129, 3, 2)
    const float* uu   = (const float*)d_in[3];  // (129, 3, 2)
    const float* data = (const float*)d_in[4];  // (512, 256, 24)
    (void)in_sizes; (void)n_in; (void)out_size;

    prep<<<NN + 1, LL>>>(anc, ins, rr, uu, data);
    hmm_fwd<<<NN / 4, 128>>>((float*)d_out);
}